// round 11
// baseline (speedup 1.0000x reference)
#include <cuda_runtime.h>
#include <cuda_bf16.h>
#include <cstdint>

#define NN 1024
#define DD 128

// ---------------- scratch (no allocations allowed) ----------------
__device__ float g_q[NN * DD];
__device__ float g_k[NN * DD];
__device__ float g_gi[NN * 3 * DD];

// progress flags (epoch-valued, monotonic => graph-replay-safe)
__device__ int g_flag[NN / 4 + 16];     // flag[c]==epoch when gi rows 4c..4c+3 ready
__device__ int g_epoch_att[NN / 4];     // per att+gi CTA launch counters
__device__ int g_epoch_gru;             // gru launch counter

// ---------------- helpers ----------------
__device__ __forceinline__ float tanh_apx(float x) {
    float y;
    asm("tanh.approx.f32 %0, %1;" : "=f"(y) : "f"(x));
    return y;
}
// sigmoid via one MUFU tanh (abs err ~1e-5; GRU is strongly contracting)
__device__ __forceinline__ float sig_apx(float x) {
    return fmaf(0.5f, tanh_apx(0.5f * x), 0.5f);
}

__device__ __forceinline__ unsigned long long ffma2(unsigned long long a,
                                                    unsigned long long b,
                                                    unsigned long long c) {
    unsigned long long d;
    asm("fma.rn.f32x2 %0, %1, %2, %3;" : "=l"(d) : "l"(a), "l"(b), "l"(c));
    return d;
}
__device__ __forceinline__ unsigned long long fadd2(unsigned long long a,
                                                    unsigned long long b) {
    unsigned long long d;
    asm("add.rn.f32x2 %0, %1, %2;" : "=l"(d) : "l"(a), "l"(b));
    return d;
}
__device__ __forceinline__ float f2lo(unsigned long long a) {
    return __uint_as_float((unsigned)(a & 0xffffffffull));
}
__device__ __forceinline__ float f2hi(unsigned long long a) {
    return __uint_as_float((unsigned)(a >> 32));
}

// block reductions for 384 threads (12 warps)
__device__ __forceinline__ float block_reduce_max(float v) {
    __shared__ float red[12];
    #pragma unroll
    for (int o = 16; o; o >>= 1) v = fmaxf(v, __shfl_xor_sync(0xffffffffu, v, o));
    if ((threadIdx.x & 31) == 0) red[threadIdx.x >> 5] = v;
    __syncthreads();
    float r = red[0];
    #pragma unroll
    for (int i = 1; i < 12; i++) r = fmaxf(r, red[i]);
    __syncthreads();
    return r;
}

__device__ __forceinline__ float block_reduce_sum(float v) {
    __shared__ float red[12];
    #pragma unroll
    for (int o = 16; o; o >>= 1) v += __shfl_xor_sync(0xffffffffu, v, o);
    if ((threadIdx.x & 31) == 0) red[threadIdx.x >> 5] = v;
    __syncthreads();
    float r = red[0];
    #pragma unroll
    for (int i = 1; i < 12; i++) r += red[i];
    __syncthreads();
    return r;
}

// ---------------- kernel 1: q = X@Wq^T, k = X@Wk^T (4 rows per CTA) ---------
__global__ void __launch_bounds__(256) qk_kernel(const float* __restrict__ X,
                                                 const float* __restrict__ Wq,
                                                 const float* __restrict__ Wk) {
    __shared__ __align__(16) float xs[4][DD];
    const int n0 = blockIdx.x * 4;
    const int tid = threadIdx.x;
    for (int idx = tid; idx < 4 * DD; idx += 256)
        xs[idx >> 7][idx & 127] = X[(n0 + (idx >> 7)) * DD + (idx & 127)];
    __syncthreads();

    const int s = tid >> 7;
    const int d = tid & 127;
    const float4* W4 = (const float4*)((s ? Wk : Wq) + d * DD);
    float acc[4] = {0.f, 0.f, 0.f, 0.f};

    #pragma unroll 8
    for (int c = 0; c < 32; c++) {
        float4 w = W4[c];
        #pragma unroll
        for (int r = 0; r < 4; r++) {
            float4 x = *(const float4*)&xs[r][c * 4];
            acc[r] += w.x * x.x + w.y * x.y + w.z * x.z + w.w * x.w;
        }
    }
    float* dst = s ? g_k : g_q;
    #pragma unroll
    for (int r = 0; r < 4; r++) dst[(n0 + r) * DD + d] = acc[r];
}

// ---------------- kernel 2: fused attention + gi, flag per 4-row chunk -------
__global__ void __launch_bounds__(384) att_gi_kernel(const float* __restrict__ X,
                                                     const float* __restrict__ v,
                                                     const float* __restrict__ w_ih,
                                                     const float* __restrict__ b_ih,
                                                     const float* __restrict__ b_hh) {
    __shared__ __align__(16) float q_s[4][DD];
    __shared__ __align__(16) float v_s[DD];
    __shared__ float sc[4][NN];
    __shared__ float inv_s[4];
    __shared__ __align__(16) float x4_s[4][DD];
    __shared__ __align__(16) float att_s[4][DD];
    __shared__ float part1[4][DD];
    __shared__ float part2[4][DD];
    __shared__ int ep_s;

    const int blk = blockIdx.x;
    const int i0 = blk * 4;
    const int tid = threadIdx.x;

    if (tid == 0) ep_s = atomicAdd(&g_epoch_att[blk], 1) + 1;

    for (int idx = tid; idx < 4 * DD; idx += 384) {
        q_s[idx >> 7][idx & 127] = g_q[(i0 + (idx >> 7)) * DD + (idx & 127)];
        x4_s[idx >> 7][idx & 127] = X[(i0 + (idx >> 7)) * DD + (idx & 127)];
    }
    if (tid < DD) v_s[tid] = v[tid];
    __syncthreads();

    // ---- phase A: scores ----
    for (int j = i0 + tid; j < NN; j += 384) {
        const float4* kr = (const float4*)(g_k + j * DD);
        float a0 = 0.f, a1 = 0.f, a2 = 0.f, a3 = 0.f;
        #pragma unroll 4
        for (int c = 0; c < 32; c++) {
            float4 kk = kr[c];
            float4 vv = *(const float4*)&v_s[c * 4];
            float4 q0 = *(const float4*)&q_s[0][c * 4];
            float4 q1 = *(const float4*)&q_s[1][c * 4];
            float4 q2 = *(const float4*)&q_s[2][c * 4];
            float4 q3 = *(const float4*)&q_s[3][c * 4];
            a0 += vv.x * tanh_apx(q0.x + kk.x) + vv.y * tanh_apx(q0.y + kk.y)
                + vv.z * tanh_apx(q0.z + kk.z) + vv.w * tanh_apx(q0.w + kk.w);
            a1 += vv.x * tanh_apx(q1.x + kk.x) + vv.y * tanh_apx(q1.y + kk.y)
                + vv.z * tanh_apx(q1.z + kk.z) + vv.w * tanh_apx(q1.w + kk.w);
            a2 += vv.x * tanh_apx(q2.x + kk.x) + vv.y * tanh_apx(q2.y + kk.y)
                + vv.z * tanh_apx(q2.z + kk.z) + vv.w * tanh_apx(q2.w + kk.w);
            a3 += vv.x * tanh_apx(q3.x + kk.x) + vv.y * tanh_apx(q3.y + kk.y)
                + vv.z * tanh_apx(q3.z + kk.z) + vv.w * tanh_apx(q3.w + kk.w);
        }
        const int jj = j - i0;
        sc[0][jj] = a0; sc[1][jj] = a1; sc[2][jj] = a2; sc[3][jj] = a3;
    }
    __syncthreads();

    // ---- phase B: per-row softmax over the suffix ----
    const int L = NN - i0;
    for (int r = 0; r < 4; r++) {
        float m = -1e30f;
        for (int idx = tid; idx < L; idx += 384) m = fmaxf(m, sc[r][idx]);
        const float bm = block_reduce_max(m);
        float ssum = 0.f;
        for (int idx = tid; idx < L; idx += 384) {
            float e = (idx < r) ? 0.0f : __expf(sc[r][idx] - bm);
            sc[r][idx] = e;
            ssum += e;
        }
        const float bs = block_reduce_sum(ssum);
        if (tid == 0) inv_s[r] = 1.0f / bs;
    }
    __syncthreads();

    // ---- phase C: att rows -> att_s ----
    {
        const int d = tid & 127;
        const int s3 = tid >> 7;     // 0,1,2
        float a[4] = {0.f, 0.f, 0.f, 0.f};
        for (int j = i0 + s3; j < NN; j += 3) {
            const float x = X[j * DD + d];
            const int jj = j - i0;
            a[0] += sc[0][jj] * x;
            a[1] += sc[1][jj] * x;
            a[2] += sc[2][jj] * x;
            a[3] += sc[3][jj] * x;
        }
        if (s3 == 1) {
            #pragma unroll
            for (int r = 0; r < 4; r++) part1[r][d] = a[r];
        } else if (s3 == 2) {
            #pragma unroll
            for (int r = 0; r < 4; r++) part2[r][d] = a[r];
        }
        __syncthreads();
        if (s3 == 0) {
            #pragma unroll
            for (int r = 0; r < 4; r++)
                att_s[r][d] = (a[r] + part1[r][d] + part2[r][d]) * inv_s[r];
        }
        __syncthreads();
    }

    // ---- phase D: gi rows (one gate per thread, 4 time rows) ----
    {
        const float4* w4 = (const float4*)(w_ih + tid * (2 * DD));
        float acc[4] = {0.f, 0.f, 0.f, 0.f};
        #pragma unroll 4
        for (int c = 0; c < 32; c++) {       // X half
            float4 w = w4[c];
            #pragma unroll
            for (int r = 0; r < 4; r++) {
                float4 iv = *(const float4*)&x4_s[r][c * 4];
                acc[r] += w.x * iv.x + w.y * iv.y + w.z * iv.z + w.w * iv.w;
            }
        }
        #pragma unroll 4
        for (int c = 0; c < 32; c++) {       // att half
            float4 w = w4[32 + c];
            #pragma unroll
            for (int r = 0; r < 4; r++) {
                float4 iv = *(const float4*)&att_s[r][c * 4];
                acc[r] += w.x * iv.x + w.y * iv.y + w.z * iv.z + w.w * iv.w;
            }
        }
        const float b = b_ih[tid] + ((tid < 2 * DD) ? b_hh[tid] : 0.0f);
        #pragma unroll
        for (int r = 0; r < 4; r++) g_gi[(i0 + r) * 384 + tid] = acc[r] + b;
    }

    __threadfence();
    __syncthreads();
    if (tid == 0) *(volatile int*)&g_flag[blk] = ep_s;
}

// ---------------- kernel 3: sequential GRU, split-K lane pairs ---------------
// 768 threads = 24 warps (6/SMSP for latency hiding). Warp w owns rows
// [16w, 16w+16); lanes 2j/2j+1 hold the two 64-column halves of row 16w+j.
// Row layout: lrow 0-127 = n-gate rows (+ serial tail), 128-255 = r, 256-383 = z.
// Each thread: 32 FFMA2 (weights in regs) + 16 broadcast LDS.128 of its h half;
// halves merge with one shfl.xor(1). Same port floor as before; 2x the warps.
// Warp 23 polls gi flags (one per lane) in its dead time after bar.arrive(1).
__global__ void __launch_bounds__(768, 1) gru_kernel(const float* __restrict__ w_hh,
                                                     const float* __restrict__ b_hh,
                                                     float* __restrict__ out) {
    __shared__ __align__(16) float h_s[DD];
    __shared__ float r_s[DD];
    __shared__ float z_s[DD];
    __shared__ int epoch_s;

    const int t = threadIdx.x;
    const int lane = t & 31;
    const int half = lane & 1;
    const int lrow = (t >> 5) * 16 + (lane >> 1);      // 0..383
    const bool is_n = (lrow < DD);
    const int g = lrow & 127;
    const int wrow = is_n ? (2 * DD + lrow) : (lrow - DD);  // own w_hh / gi row
    const bool writer = (half == 0);

    if (t == 0) epoch_s = atomicAdd(&g_epoch_gru, 1) + 1;

    // weights: this thread's 64-column half of its row (32 packed pairs)
    unsigned long long w2[32];
    const unsigned long long* wp =
        (const unsigned long long*)(w_hh + wrow * DD + half * 64);
    #pragma unroll
    for (int i = 0; i < 32; i++) w2[i] = wp[i];
    const float bh = is_n ? b_hh[2 * DD + g] : 0.0f;   // r/z bias folded in gi

    if (t < DD) h_s[t] = 0.0f;
    __syncthreads();
    const int epoch = epoch_s;

    // this thread's h half as 16B chunks
    const ulonglong2* h2 = (const ulonglong2*)(h_s + half * 64);

    // initial wait: chunks 0..8 (steps 0..31 plus prefetch), parallel flags
    if (t <= 8) {
        volatile int* f = g_flag;
        while (f[t] < epoch) __nanosleep(32);
    }
    __syncthreads();

    float gi_cur = g_gi[wrow];   // step 0 gate input for this row
    float hreg = 0.0f;           // n-threads: own h element (both lanes track it)

    for (int step = 0; step < NN; step++) {
        // prefetch next step's gi (hidden under the matvec)
        float gi_next = 0.0f;
        if (step + 1 < NN) gi_next = g_gi[(step + 1) * 384 + wrow];

        // half-dot: 32 packed MACs over this thread's 64 columns
        unsigned long long a0 = 0ull, a1 = 0ull, a2 = 0ull, a3 = 0ull;
        #pragma unroll
        for (int i = 0; i < 8; i++) {
            ulonglong2 hA = h2[2 * i];
            ulonglong2 hB = h2[2 * i + 1];
            a0 = ffma2(w2[4 * i + 0], hA.x, a0);
            a1 = ffma2(w2[4 * i + 1], hA.y, a1);
            a2 = ffma2(w2[4 * i + 2], hB.x, a2);
            a3 = ffma2(w2[4 * i + 3], hB.y, a3);
        }
        const unsigned long long p = fadd2(fadd2(a0, a1), fadd2(a2, a3));
        const float part = f2lo(p) + f2hi(p);
        // merge the two halves: both lanes end with the full dot product
        const float s = part + __shfl_xor_sync(0xffffffffu, part, 1) + bh;

        if (!is_n) {
            // r/z rows: sigmoid locally, publish (even lane), arrive
            const float val = sig_apx(gi_cur + s);
            if (writer) {
                if (lrow < 2 * DD) r_s[g] = val; else z_s[g] = val;
            }
            asm volatile("bar.arrive 1, 768;" ::: "memory");
            // warp 23: advance the gi readiness window in its dead time
            if (t >= 736 && (step & 31) == 0 && step) {
                const int l = t - 736;
                if (l <= 8) {
                    int c = (step >> 2) + l;
                    if (c > 255) c = 255;
                    volatile int* f = g_flag;
                    while (f[c] < epoch) __nanosleep(32);
                }
            }
        } else {
            // n rows: wait for r/z, then the serial tail (both lanes compute)
            asm volatile("bar.sync 1, 768;" ::: "memory");
            const float rr  = r_s[g];
            const float zz  = z_s[g];
            const float nst = tanh_apx(fmaf(rr, s, gi_cur));   // s includes b_hh_n
            const float hv  = fmaf(zz, hreg - nst, nst);       // (1-z)n + z h
            hreg = hv;
            if (writer) {
                h_s[g] = hv;
                out[step * DD + g] = hv;
            }
        }
        // everyone: h must be written before the next matvec
        asm volatile("bar.sync 2, 768;" ::: "memory");
        gi_cur = gi_next;
    }
}

// ---------------- launch ----------------
extern "C" void kernel_launch(void* const* d_in, const int* in_sizes, int n_in,
                              void* d_out, int out_size) {
    const float* X    = (const float*)d_in[0];
    const float* Wq   = (const float*)d_in[1];
    const float* Wk   = (const float*)d_in[2];
    const float* v    = (const float*)d_in[3];
    const float* w_ih = (const float*)d_in[4];
    const float* w_hh = (const float*)d_in[5];
    const float* b_ih = (const float*)d_in[6];
    const float* b_hh = (const float*)d_in[7];
    float* out = (float*)d_out;

    // fork: prologue (qk -> att+gi) on a side stream; GRU starts immediately on
    // the main stream and consumes gi chunks via epoch flags.
    cudaStream_t s2;
    cudaStreamCreateWithFlags(&s2, cudaStreamNonBlocking);
    cudaEvent_t e1, e2;
    cudaEventCreateWithFlags(&e1, cudaEventDisableTiming);
    cudaEventCreateWithFlags(&e2, cudaEventDisableTiming);

    cudaEventRecord(e1, 0);
    cudaStreamWaitEvent(s2, e1, 0);

    qk_kernel<<<NN / 4, 256, 0, s2>>>(X, Wq, Wk);
    att_gi_kernel<<<NN / 4, 384, 0, s2>>>(X, v, w_ih, b_ih, b_hh);
    cudaEventRecord(e2, s2);

    gru_kernel<<<1, 768>>>(w_hh, b_hh, out);

    cudaStreamWaitEvent(0, e2, 0);
}

// round 12
// speedup vs baseline: 2.3331x; 2.3331x over previous
#include <cuda_runtime.h>
#include <cuda_bf16.h>
#include <cstdint>

#define NN 1024
#define DD 128

// ---------------- scratch (no allocations allowed) ----------------
__device__ float g_q[NN * DD];
__device__ float g_k[NN * DD];
__device__ float g_gi[NN * 3 * DD];

// progress flags (epoch-valued, monotonic => graph-replay-safe)
__device__ int g_flag[NN / 4 + 16];     // flag[c]==epoch when gi rows 4c..4c+3 ready
__device__ int g_epoch_att[NN / 4];     // per att+gi CTA launch counters
__device__ int g_epoch_gru;             // gru launch counter

// ---------------- helpers ----------------
__device__ __forceinline__ float tanh_apx(float x) {
    float y;
    asm("tanh.approx.f32 %0, %1;" : "=f"(y) : "f"(x));
    return y;
}
// sigmoid via one MUFU tanh (abs err ~1e-5; GRU is strongly contracting)
__device__ __forceinline__ float sig_apx(float x) {
    return fmaf(0.5f, tanh_apx(0.5f * x), 0.5f);
}

__device__ __forceinline__ unsigned long long ffma2(unsigned long long a,
                                                    unsigned long long b,
                                                    unsigned long long c) {
    unsigned long long d;
    asm("fma.rn.f32x2 %0, %1, %2, %3;" : "=l"(d) : "l"(a), "l"(b), "l"(c));
    return d;
}
__device__ __forceinline__ unsigned long long fadd2(unsigned long long a,
                                                    unsigned long long b) {
    unsigned long long d;
    asm("add.rn.f32x2 %0, %1, %2;" : "=l"(d) : "l"(a), "l"(b));
    return d;
}
__device__ __forceinline__ float f2lo(unsigned long long a) {
    return __uint_as_float((unsigned)(a & 0xffffffffull));
}
__device__ __forceinline__ float f2hi(unsigned long long a) {
    return __uint_as_float((unsigned)(a >> 32));
}

// block reductions for 384 threads (12 warps)
__device__ __forceinline__ float block_reduce_max(float v) {
    __shared__ float red[12];
    #pragma unroll
    for (int o = 16; o; o >>= 1) v = fmaxf(v, __shfl_xor_sync(0xffffffffu, v, o));
    if ((threadIdx.x & 31) == 0) red[threadIdx.x >> 5] = v;
    __syncthreads();
    float r = red[0];
    #pragma unroll
    for (int i = 1; i < 12; i++) r = fmaxf(r, red[i]);
    __syncthreads();
    return r;
}

__device__ __forceinline__ float block_reduce_sum(float v) {
    __shared__ float red[12];
    #pragma unroll
    for (int o = 16; o; o >>= 1) v += __shfl_xor_sync(0xffffffffu, v, o);
    if ((threadIdx.x & 31) == 0) red[threadIdx.x >> 5] = v;
    __syncthreads();
    float r = red[0];
    #pragma unroll
    for (int i = 1; i < 12; i++) r += red[i];
    __syncthreads();
    return r;
}

// ---------------- kernel 1: q = X@Wq^T, k = X@Wk^T (4 rows per CTA) ---------
__global__ void __launch_bounds__(256) qk_kernel(const float* __restrict__ X,
                                                 const float* __restrict__ Wq,
                                                 const float* __restrict__ Wk) {
    __shared__ __align__(16) float xs[4][DD];
    const int n0 = blockIdx.x * 4;
    const int tid = threadIdx.x;
    for (int idx = tid; idx < 4 * DD; idx += 256)
        xs[idx >> 7][idx & 127] = X[(n0 + (idx >> 7)) * DD + (idx & 127)];
    __syncthreads();

    const int s = tid >> 7;
    const int d = tid & 127;
    const float4* W4 = (const float4*)((s ? Wk : Wq) + d * DD);
    float acc[4] = {0.f, 0.f, 0.f, 0.f};

    #pragma unroll 8
    for (int c = 0; c < 32; c++) {
        float4 w = W4[c];
        #pragma unroll
        for (int r = 0; r < 4; r++) {
            float4 x = *(const float4*)&xs[r][c * 4];
            acc[r] += w.x * x.x + w.y * x.y + w.z * x.z + w.w * x.w;
        }
    }
    float* dst = s ? g_k : g_q;
    #pragma unroll
    for (int r = 0; r < 4; r++) dst[(n0 + r) * DD + d] = acc[r];
}

// ---------------- kernel 2: fused attention + gi, flag per 4-row chunk -------
__global__ void __launch_bounds__(384) att_gi_kernel(const float* __restrict__ X,
                                                     const float* __restrict__ v,
                                                     const float* __restrict__ w_ih,
                                                     const float* __restrict__ b_ih,
                                                     const float* __restrict__ b_hh) {
    __shared__ __align__(16) float q_s[4][DD];
    __shared__ __align__(16) float v_s[DD];
    __shared__ float sc[4][NN];
    __shared__ float inv_s[4];
    __shared__ __align__(16) float x4_s[4][DD];
    __shared__ __align__(16) float att_s[4][DD];
    __shared__ float part1[4][DD];
    __shared__ float part2[4][DD];
    __shared__ int ep_s;

    const int blk = blockIdx.x;
    const int i0 = blk * 4;
    const int tid = threadIdx.x;

    if (tid == 0) ep_s = atomicAdd(&g_epoch_att[blk], 1) + 1;

    for (int idx = tid; idx < 4 * DD; idx += 384) {
        q_s[idx >> 7][idx & 127] = g_q[(i0 + (idx >> 7)) * DD + (idx & 127)];
        x4_s[idx >> 7][idx & 127] = X[(i0 + (idx >> 7)) * DD + (idx & 127)];
    }
    if (tid < DD) v_s[tid] = v[tid];
    __syncthreads();

    // ---- phase A: scores ----
    for (int j = i0 + tid; j < NN; j += 384) {
        const float4* kr = (const float4*)(g_k + j * DD);
        float a0 = 0.f, a1 = 0.f, a2 = 0.f, a3 = 0.f;
        #pragma unroll 4
        for (int c = 0; c < 32; c++) {
            float4 kk = kr[c];
            float4 vv = *(const float4*)&v_s[c * 4];
            float4 q0 = *(const float4*)&q_s[0][c * 4];
            float4 q1 = *(const float4*)&q_s[1][c * 4];
            float4 q2 = *(const float4*)&q_s[2][c * 4];
            float4 q3 = *(const float4*)&q_s[3][c * 4];
            a0 += vv.x * tanh_apx(q0.x + kk.x) + vv.y * tanh_apx(q0.y + kk.y)
                + vv.z * tanh_apx(q0.z + kk.z) + vv.w * tanh_apx(q0.w + kk.w);
            a1 += vv.x * tanh_apx(q1.x + kk.x) + vv.y * tanh_apx(q1.y + kk.y)
                + vv.z * tanh_apx(q1.z + kk.z) + vv.w * tanh_apx(q1.w + kk.w);
            a2 += vv.x * tanh_apx(q2.x + kk.x) + vv.y * tanh_apx(q2.y + kk.y)
                + vv.z * tanh_apx(q2.z + kk.z) + vv.w * tanh_apx(q2.w + kk.w);
            a3 += vv.x * tanh_apx(q3.x + kk.x) + vv.y * tanh_apx(q3.y + kk.y)
                + vv.z * tanh_apx(q3.z + kk.z) + vv.w * tanh_apx(q3.w + kk.w);
        }
        const int jj = j - i0;
        sc[0][jj] = a0; sc[1][jj] = a1; sc[2][jj] = a2; sc[3][jj] = a3;
    }
    __syncthreads();

    // ---- phase B: per-row softmax over the suffix ----
    const int L = NN - i0;
    for (int r = 0; r < 4; r++) {
        float m = -1e30f;
        for (int idx = tid; idx < L; idx += 384) m = fmaxf(m, sc[r][idx]);
        const float bm = block_reduce_max(m);
        float ssum = 0.f;
        for (int idx = tid; idx < L; idx += 384) {
            float e = (idx < r) ? 0.0f : __expf(sc[r][idx] - bm);
            sc[r][idx] = e;
            ssum += e;
        }
        const float bs = block_reduce_sum(ssum);
        if (tid == 0) inv_s[r] = 1.0f / bs;
    }
    __syncthreads();

    // ---- phase C: att rows -> att_s ----
    {
        const int d = tid & 127;
        const int s3 = tid >> 7;     // 0,1,2
        float a[4] = {0.f, 0.f, 0.f, 0.f};
        for (int j = i0 + s3; j < NN; j += 3) {
            const float x = X[j * DD + d];
            const int jj = j - i0;
            a[0] += sc[0][jj] * x;
            a[1] += sc[1][jj] * x;
            a[2] += sc[2][jj] * x;
            a[3] += sc[3][jj] * x;
        }
        if (s3 == 1) {
            #pragma unroll
            for (int r = 0; r < 4; r++) part1[r][d] = a[r];
        } else if (s3 == 2) {
            #pragma unroll
            for (int r = 0; r < 4; r++) part2[r][d] = a[r];
        }
        __syncthreads();
        if (s3 == 0) {
            #pragma unroll
            for (int r = 0; r < 4; r++)
                att_s[r][d] = (a[r] + part1[r][d] + part2[r][d]) * inv_s[r];
        }
        __syncthreads();
    }

    // ---- phase D: gi rows (one gate per thread, 4 time rows) ----
    {
        const float4* w4 = (const float4*)(w_ih + tid * (2 * DD));
        float acc[4] = {0.f, 0.f, 0.f, 0.f};
        #pragma unroll 4
        for (int c = 0; c < 32; c++) {       // X half
            float4 w = w4[c];
            #pragma unroll
            for (int r = 0; r < 4; r++) {
                float4 iv = *(const float4*)&x4_s[r][c * 4];
                acc[r] += w.x * iv.x + w.y * iv.y + w.z * iv.z + w.w * iv.w;
            }
        }
        #pragma unroll 4
        for (int c = 0; c < 32; c++) {       // att half
            float4 w = w4[32 + c];
            #pragma unroll
            for (int r = 0; r < 4; r++) {
                float4 iv = *(const float4*)&att_s[r][c * 4];
                acc[r] += w.x * iv.x + w.y * iv.y + w.z * iv.z + w.w * iv.w;
            }
        }
        const float b = b_ih[tid] + ((tid < 2 * DD) ? b_hh[tid] : 0.0f);
        #pragma unroll
        for (int r = 0; r < 4; r++) g_gi[(i0 + r) * 384 + tid] = acc[r] + b;
    }

    __threadfence();
    __syncthreads();
    if (tid == 0) *(volatile int*)&g_flag[blk] = ep_s;
}

// ---------------- kernel 3: sequential GRU (overlapped consumer) -------------
// Warps 0-3  (t <  128): n-gate rows + serial tail (h in register).
// Warps 4-11 (t >= 128): r/z-gate rows, sigmoid pre-barrier.
// Warp 11 polls gi flags (one flag per lane, parallel) in its dead time.
// Matvec uses 8 independent accumulator chains (dep distance 8 >= FFMA2 lat)
// with batched LDS.128 groups for MLP overlap.
__global__ void __launch_bounds__(384, 1) gru_kernel(const float* __restrict__ w_hh,
                                                     const float* __restrict__ b_hh,
                                                     float* __restrict__ out) {
    __shared__ __align__(16) float h_s[DD];
    __shared__ float r_s[DD];
    __shared__ float z_s[DD];
    __shared__ int epoch_s;

    const int t = threadIdx.x;
    const bool is_n = (t < DD);
    const int g = t & 127;
    const int wrow = is_n ? (2 * DD + t) : (t - DD);   // own w_hh / gi row

    if (t == 0) epoch_s = atomicAdd(&g_epoch_gru, 1) + 1;

    unsigned long long w2[64];
    const unsigned long long* wp = (const unsigned long long*)(w_hh + wrow * DD);
    #pragma unroll
    for (int i = 0; i < 64; i++) w2[i] = wp[i];
    const float bh = is_n ? b_hh[2 * DD + t] : 0.0f;   // r/z bias folded in gi

    if (t < DD) h_s[t] = 0.0f;
    __syncthreads();
    const int epoch = epoch_s;

    const ulonglong2* h2 = (const ulonglong2*)h_s;

    // initial wait: chunks 0..8 (steps 0..31 plus prefetch), parallel flags
    if (t <= 8) {
        volatile int* f = g_flag;
        while (f[t] < epoch) __nanosleep(32);
    }
    __syncthreads();

    float gi_cur = g_gi[wrow];   // step 0 gate input for this thread's own row
    float hreg = 0.0f;           // n-threads: own h element in a register

    for (int step = 0; step < NN; step++) {
        // prefetch next step's gi (hidden under the matvec)
        float gi_next = 0.0f;
        if (step + 1 < NN) gi_next = g_gi[(step + 1) * 384 + wrow];

        // s = bias + w_hh[wrow,:] . h
        // 8 accumulator chains; each group: 4 batched LDS.128 + 8 FFMA2
        unsigned long long a0 = 0ull, a1 = 0ull, a2 = 0ull, a3 = 0ull;
        unsigned long long a4 = 0ull, a5 = 0ull, a6 = 0ull, a7 = 0ull;
        #pragma unroll
        for (int i = 0; i < 8; i++) {
            ulonglong2 hA = h2[4 * i];
            ulonglong2 hB = h2[4 * i + 1];
            ulonglong2 hC = h2[4 * i + 2];
            ulonglong2 hD = h2[4 * i + 3];
            a0 = ffma2(w2[8 * i + 0], hA.x, a0);
            a1 = ffma2(w2[8 * i + 1], hA.y, a1);
            a2 = ffma2(w2[8 * i + 2], hB.x, a2);
            a3 = ffma2(w2[8 * i + 3], hB.y, a3);
            a4 = ffma2(w2[8 * i + 4], hC.x, a4);
            a5 = ffma2(w2[8 * i + 5], hC.y, a5);
            a6 = ffma2(w2[8 * i + 6], hD.x, a6);
            a7 = ffma2(w2[8 * i + 7], hD.y, a7);
        }
        const unsigned long long p =
            fadd2(fadd2(fadd2(a0, a1), fadd2(a2, a3)),
                  fadd2(fadd2(a4, a5), fadd2(a6, a7)));
        const float s = f2lo(p) + f2hi(p) + bh;

        if (!is_n) {
            // r/z warps: sigmoid locally, publish, arrive (non-blocking)
            const float val = sig_apx(gi_cur + s);
            if (t < 2 * DD) r_s[g] = val; else z_s[g] = val;
            asm volatile("bar.arrive 1, 384;" ::: "memory");
            // warp 11: advance the gi readiness window in its dead time
            if (t >= 352 && (step & 31) == 0 && step) {
                const int l = t - 352;
                if (l <= 8) {
                    int c = (step >> 2) + l;
                    if (c > 255) c = 255;
                    volatile int* f = g_flag;
                    while (f[c] < epoch) __nanosleep(32);
                }
            }
        } else {
            // n warps: wait for r/z, then the serial tail
            asm volatile("bar.sync 1, 384;" ::: "memory");
            const float rr  = r_s[g];
            const float zz  = z_s[g];
            const float nst = tanh_apx(fmaf(rr, s, gi_cur));   // s includes b_hh_n
            const float hv  = fmaf(zz, hreg - nst, nst);       // (1-z)n + z h
            hreg = hv;
            h_s[g] = hv;
            out[step * DD + g] = hv;
        }
        // everyone: h must be written before the next matvec
        asm volatile("bar.sync 2, 384;" ::: "memory");
        gi_cur = gi_next;
    }
}

// ---------------- launch ----------------
extern "C" void kernel_launch(void* const* d_in, const int* in_sizes, int n_in,
                              void* d_out, int out_size) {
    const float* X    = (const float*)d_in[0];
    const float* Wq   = (const float*)d_in[1];
    const float* Wk   = (const float*)d_in[2];
    const float* v    = (const float*)d_in[3];
    const float* w_ih = (const float*)d_in[4];
    const float* w_hh = (const float*)d_in[5];
    const float* b_ih = (const float*)d_in[6];
    const float* b_hh = (const float*)d_in[7];
    float* out = (float*)d_out;

    // fork: prologue (qk -> att+gi) on a side stream; GRU starts immediately on
    // the main stream and consumes gi chunks via epoch flags.
    cudaStream_t s2;
    cudaStreamCreateWithFlags(&s2, cudaStreamNonBlocking);
    cudaEvent_t e1, e2;
    cudaEventCreateWithFlags(&e1, cudaEventDisableTiming);
    cudaEventCreateWithFlags(&e2, cudaEventDisableTiming);

    cudaEventRecord(e1, 0);
    cudaStreamWaitEvent(s2, e1, 0);

    qk_kernel<<<NN / 4, 256, 0, s2>>>(X, Wq, Wk);
    att_gi_kernel<<<NN / 4, 384, 0, s2>>>(X, v, w_ih, b_ih, b_hh);
    cudaEventRecord(e2, s2);

    gru_kernel<<<1, 384>>>(w_hh, b_hh, out);

    cudaStreamWaitEvent(0, e2, 0);
}

// round 13
// speedup vs baseline: 2.5794x; 1.1055x over previous
#include <cuda_runtime.h>
#include <cuda_bf16.h>
#include <cuda_fp16.h>
#include <cstdint>

#define NN 1024
#define DD 128

// ---------------- scratch (no allocations allowed) ----------------
__device__ float g_q[NN * DD];
__device__ float g_k[NN * DD];
__device__ float g_gi[NN * 3 * DD];

// progress flags (epoch-valued, monotonic => graph-replay-safe)
__device__ int g_flag[NN / 4 + 16];     // flag[c]==epoch when gi rows 4c..4c+3 ready
__device__ int g_epoch_att[NN / 4];     // per att+gi CTA launch counters
__device__ int g_epoch_gru;             // gru launch counter

// ---------------- helpers ----------------
__device__ __forceinline__ float tanh_apx(float x) {
    float y;
    asm("tanh.approx.f32 %0, %1;" : "=f"(y) : "f"(x));
    return y;
}
// sigmoid via one MUFU tanh (abs err ~1e-5; GRU is strongly contracting)
__device__ __forceinline__ float sig_apx(float x) {
    return fmaf(0.5f, tanh_apx(0.5f * x), 0.5f);
}

__device__ __forceinline__ unsigned long long ffma2(unsigned long long a,
                                                    unsigned long long b,
                                                    unsigned long long c) {
    unsigned long long d;
    asm("fma.rn.f32x2 %0, %1, %2, %3;" : "=l"(d) : "l"(a), "l"(b), "l"(c));
    return d;
}
__device__ __forceinline__ unsigned long long fadd2(unsigned long long a,
                                                    unsigned long long b) {
    unsigned long long d;
    asm("add.rn.f32x2 %0, %1, %2;" : "=l"(d) : "l"(a), "l"(b));
    return d;
}
__device__ __forceinline__ float f2lo(unsigned long long a) {
    return __uint_as_float((unsigned)(a & 0xffffffffull));
}
__device__ __forceinline__ float f2hi(unsigned long long a) {
    return __uint_as_float((unsigned)(a >> 32));
}
// half2 views of a packed u64 (register-free reinterpret)
__device__ __forceinline__ __half2 h2lo(unsigned long long a) {
    unsigned x = (unsigned)(a & 0xffffffffull);
    return *(__half2*)&x;
}
__device__ __forceinline__ __half2 h2hi(unsigned long long a) {
    unsigned x = (unsigned)(a >> 32);
    return *(__half2*)&x;
}

// block reductions for 384 threads (12 warps)
__device__ __forceinline__ float block_reduce_max(float v) {
    __shared__ float red[12];
    #pragma unroll
    for (int o = 16; o; o >>= 1) v = fmaxf(v, __shfl_xor_sync(0xffffffffu, v, o));
    if ((threadIdx.x & 31) == 0) red[threadIdx.x >> 5] = v;
    __syncthreads();
    float r = red[0];
    #pragma unroll
    for (int i = 1; i < 12; i++) r = fmaxf(r, red[i]);
    __syncthreads();
    return r;
}

__device__ __forceinline__ float block_reduce_sum(float v) {
    __shared__ float red[12];
    #pragma unroll
    for (int o = 16; o; o >>= 1) v += __shfl_xor_sync(0xffffffffu, v, o);
    if ((threadIdx.x & 31) == 0) red[threadIdx.x >> 5] = v;
    __syncthreads();
    float r = red[0];
    #pragma unroll
    for (int i = 1; i < 12; i++) r += red[i];
    __syncthreads();
    return r;
}

// ---------------- kernel 1: q = X@Wq^T, k = X@Wk^T (4 rows per CTA) ---------
__global__ void __launch_bounds__(256) qk_kernel(const float* __restrict__ X,
                                                 const float* __restrict__ Wq,
                                                 const float* __restrict__ Wk) {
    __shared__ __align__(16) float xs[4][DD];
    const int n0 = blockIdx.x * 4;
    const int tid = threadIdx.x;
    for (int idx = tid; idx < 4 * DD; idx += 256)
        xs[idx >> 7][idx & 127] = X[(n0 + (idx >> 7)) * DD + (idx & 127)];
    __syncthreads();

    const int s = tid >> 7;
    const int d = tid & 127;
    const float4* W4 = (const float4*)((s ? Wk : Wq) + d * DD);
    float acc[4] = {0.f, 0.f, 0.f, 0.f};

    #pragma unroll 8
    for (int c = 0; c < 32; c++) {
        float4 w = W4[c];
        #pragma unroll
        for (int r = 0; r < 4; r++) {
            float4 x = *(const float4*)&xs[r][c * 4];
            acc[r] += w.x * x.x + w.y * x.y + w.z * x.z + w.w * x.w;
        }
    }
    float* dst = s ? g_k : g_q;
    #pragma unroll
    for (int r = 0; r < 4; r++) dst[(n0 + r) * DD + d] = acc[r];
}

// ---------------- kernel 2: fused attention + gi, flag per 4-row chunk -------
__global__ void __launch_bounds__(384) att_gi_kernel(const float* __restrict__ X,
                                                     const float* __restrict__ v,
                                                     const float* __restrict__ w_ih,
                                                     const float* __restrict__ b_ih,
                                                     const float* __restrict__ b_hh) {
    __shared__ __align__(16) float q_s[4][DD];
    __shared__ __align__(16) float v_s[DD];
    __shared__ float sc[4][NN];
    __shared__ float inv_s[4];
    __shared__ __align__(16) float x4_s[4][DD];
    __shared__ __align__(16) float att_s[4][DD];
    __shared__ float part1[4][DD];
    __shared__ float part2[4][DD];
    __shared__ int ep_s;

    const int blk = blockIdx.x;
    const int i0 = blk * 4;
    const int tid = threadIdx.x;

    if (tid == 0) ep_s = atomicAdd(&g_epoch_att[blk], 1) + 1;

    for (int idx = tid; idx < 4 * DD; idx += 384) {
        q_s[idx >> 7][idx & 127] = g_q[(i0 + (idx >> 7)) * DD + (idx & 127)];
        x4_s[idx >> 7][idx & 127] = X[(i0 + (idx >> 7)) * DD + (idx & 127)];
    }
    if (tid < DD) v_s[tid] = v[tid];
    __syncthreads();

    // ---- phase A: scores ----
    for (int j = i0 + tid; j < NN; j += 384) {
        const float4* kr = (const float4*)(g_k + j * DD);
        float a0 = 0.f, a1 = 0.f, a2 = 0.f, a3 = 0.f;
        #pragma unroll 4
        for (int c = 0; c < 32; c++) {
            float4 kk = kr[c];
            float4 vv = *(const float4*)&v_s[c * 4];
            float4 q0 = *(const float4*)&q_s[0][c * 4];
            float4 q1 = *(const float4*)&q_s[1][c * 4];
            float4 q2 = *(const float4*)&q_s[2][c * 4];
            float4 q3 = *(const float4*)&q_s[3][c * 4];
            a0 += vv.x * tanh_apx(q0.x + kk.x) + vv.y * tanh_apx(q0.y + kk.y)
                + vv.z * tanh_apx(q0.z + kk.z) + vv.w * tanh_apx(q0.w + kk.w);
            a1 += vv.x * tanh_apx(q1.x + kk.x) + vv.y * tanh_apx(q1.y + kk.y)
                + vv.z * tanh_apx(q1.z + kk.z) + vv.w * tanh_apx(q1.w + kk.w);
            a2 += vv.x * tanh_apx(q2.x + kk.x) + vv.y * tanh_apx(q2.y + kk.y)
                + vv.z * tanh_apx(q2.z + kk.z) + vv.w * tanh_apx(q2.w + kk.w);
            a3 += vv.x * tanh_apx(q3.x + kk.x) + vv.y * tanh_apx(q3.y + kk.y)
                + vv.z * tanh_apx(q3.z + kk.z) + vv.w * tanh_apx(q3.w + kk.w);
        }
        const int jj = j - i0;
        sc[0][jj] = a0; sc[1][jj] = a1; sc[2][jj] = a2; sc[3][jj] = a3;
    }
    __syncthreads();

    // ---- phase B: per-row softmax over the suffix ----
    const int L = NN - i0;
    for (int r = 0; r < 4; r++) {
        float m = -1e30f;
        for (int idx = tid; idx < L; idx += 384) m = fmaxf(m, sc[r][idx]);
        const float bm = block_reduce_max(m);
        float ssum = 0.f;
        for (int idx = tid; idx < L; idx += 384) {
            float e = (idx < r) ? 0.0f : __expf(sc[r][idx] - bm);
            sc[r][idx] = e;
            ssum += e;
        }
        const float bs = block_reduce_sum(ssum);
        if (tid == 0) inv_s[r] = 1.0f / bs;
    }
    __syncthreads();

    // ---- phase C: att rows -> att_s ----
    {
        const int d = tid & 127;
        const int s3 = tid >> 7;     // 0,1,2
        float a[4] = {0.f, 0.f, 0.f, 0.f};
        for (int j = i0 + s3; j < NN; j += 3) {
            const float x = X[j * DD + d];
            const int jj = j - i0;
            a[0] += sc[0][jj] * x;
            a[1] += sc[1][jj] * x;
            a[2] += sc[2][jj] * x;
            a[3] += sc[3][jj] * x;
        }
        if (s3 == 1) {
            #pragma unroll
            for (int r = 0; r < 4; r++) part1[r][d] = a[r];
        } else if (s3 == 2) {
            #pragma unroll
            for (int r = 0; r < 4; r++) part2[r][d] = a[r];
        }
        __syncthreads();
        if (s3 == 0) {
            #pragma unroll
            for (int r = 0; r < 4; r++)
                att_s[r][d] = (a[r] + part1[r][d] + part2[r][d]) * inv_s[r];
        }
        __syncthreads();
    }

    // ---- phase D: gi rows (one gate per thread, 4 time rows) ----
    {
        const float4* w4 = (const float4*)(w_ih + tid * (2 * DD));
        float acc[4] = {0.f, 0.f, 0.f, 0.f};
        #pragma unroll 4
        for (int c = 0; c < 32; c++) {       // X half
            float4 w = w4[c];
            #pragma unroll
            for (int r = 0; r < 4; r++) {
                float4 iv = *(const float4*)&x4_s[r][c * 4];
                acc[r] += w.x * iv.x + w.y * iv.y + w.z * iv.z + w.w * iv.w;
            }
        }
        #pragma unroll 4
        for (int c = 0; c < 32; c++) {       // att half
            float4 w = w4[32 + c];
            #pragma unroll
            for (int r = 0; r < 4; r++) {
                float4 iv = *(const float4*)&att_s[r][c * 4];
                acc[r] += w.x * iv.x + w.y * iv.y + w.z * iv.z + w.w * iv.w;
            }
        }
        const float b = b_ih[tid] + ((tid < 2 * DD) ? b_hh[tid] : 0.0f);
        #pragma unroll
        for (int r = 0; r < 4; r++) g_gi[(i0 + r) * 384 + tid] = acc[r] + b;
    }

    __threadfence();
    __syncthreads();
    if (tid == 0) *(volatile int*)&g_flag[blk] = ep_s;
}

// ---------------- kernel 3: sequential GRU (overlapped consumer) -------------
// Warps 0-3  (t <  128): n-gate rows, fp32 FFMA2 matvec + serial tail.
// Warps 4-11 (t >= 128): r/z-gate rows, fp16 HFMA2 matvec (rt 2 vs FFMA2 rt 3)
//   — sigmoid damping (slope 1/4) + GRU contraction keeps fp16 error ~1e-4.
// h is published both as fp32 (h_s, for n) and fp16x2 (h16_s, for r/z).
// Warp 11 polls gi flags (one per lane) in its dead time after bar.arrive(1).
__global__ void __launch_bounds__(384, 1) gru_kernel(const float* __restrict__ w_hh,
                                                     const float* __restrict__ b_hh,
                                                     float* __restrict__ out) {
    __shared__ __align__(16) float h_s[DD];
    __shared__ __align__(16) __half2 h16_s[DD / 2];
    __shared__ __align__(8) float2 rz_s[DD];      // .x = r gate, .y = z gate
    __shared__ int epoch_s;

    const int t = threadIdx.x;
    const bool is_n = (t < DD);
    const int g = t & 127;
    const int wrow = is_n ? (2 * DD + t) : (t - DD);   // own w_hh / gi row

    if (t == 0) epoch_s = atomicAdd(&g_epoch_gru, 1) + 1;

    // weights: n threads pack fp32 pairs in w2[0..63];
    //          r/z threads pack fp16 quads (2 half2) in w2[0..31].
    unsigned long long w2[64];
    if (is_n) {
        const unsigned long long* wp = (const unsigned long long*)(w_hh + wrow * DD);
        #pragma unroll
        for (int i = 0; i < 64; i++) w2[i] = wp[i];
    } else {
        const float2* wp = (const float2*)(w_hh + wrow * DD);
        #pragma unroll
        for (int i = 0; i < 32; i++) {
            __half2 q0 = __float22half2_rn(wp[2 * i]);
            __half2 q1 = __float22half2_rn(wp[2 * i + 1]);
            w2[i] = (unsigned long long)(*(unsigned*)&q0)
                  | ((unsigned long long)(*(unsigned*)&q1) << 32);
        }
    }
    const float bh = is_n ? b_hh[2 * DD + t] : 0.0f;   // r/z bias folded in gi

    if (t < DD) h_s[t] = 0.0f;
    if (t < DD / 2) ((unsigned*)h16_s)[t] = 0u;
    __syncthreads();
    const int epoch = epoch_s;

    const ulonglong2* h2 = (const ulonglong2*)h_s;         // fp32 pairs (n path)
    const ulonglong2* h16q = (const ulonglong2*)h16_s;     // 4 half2 per 16B

    // initial wait: chunks 0..8 (steps 0..31 plus prefetch), parallel flags
    if (t <= 8) {
        volatile int* f = g_flag;
        while (f[t] < epoch) __nanosleep(32);
    }
    __syncthreads();

    float gi_cur = g_gi[wrow];   // step 0 gate input for this thread's own row
    float hreg = 0.0f;           // n-threads: own h element in a register

    for (int step = 0; step < NN; step++) {
        // prefetch next step's gi (hidden under the matvec)
        float gi_next = 0.0f;
        if (step + 1 < NN) gi_next = g_gi[(step + 1) * 384 + wrow];

        if (!is_n) {
            // ---- r/z: fp16 HFMA2 matvec, 8 chains ----
            __half2 c0 = __float2half2_rn(0.f), c1 = c0, c2 = c0, c3 = c0;
            __half2 c4 = c0, c5 = c0, c6 = c0, c7 = c0;
            #pragma unroll
            for (int i = 0; i < 8; i++) {
                ulonglong2 hu = h16q[2 * i];        // cols 16i   .. 16i+7
                ulonglong2 hv = h16q[2 * i + 1];    // cols 16i+8 .. 16i+15
                const unsigned long long wa = w2[4 * i + 0];
                const unsigned long long wb = w2[4 * i + 1];
                const unsigned long long wc = w2[4 * i + 2];
                const unsigned long long wd = w2[4 * i + 3];
                c0 = __hfma2(h2lo(wa), h2lo(hu.x), c0);
                c1 = __hfma2(h2hi(wa), h2hi(hu.x), c1);
                c2 = __hfma2(h2lo(wb), h2lo(hu.y), c2);
                c3 = __hfma2(h2hi(wb), h2hi(hu.y), c3);
                c4 = __hfma2(h2lo(wc), h2lo(hv.x), c4);
                c5 = __hfma2(h2hi(wc), h2hi(hv.x), c5);
                c6 = __hfma2(h2lo(wd), h2lo(hv.y), c6);
                c7 = __hfma2(h2hi(wd), h2hi(hv.y), c7);
            }
            __half2 d0 = __hadd2(__hadd2(c0, c1), __hadd2(c2, c3));
            __half2 d1 = __hadd2(__hadd2(c4, c5), __hadd2(c6, c7));
            __half2 dt = __hadd2(d0, d1);
            const float s = __low2float(dt) + __high2float(dt);

            // sigmoid locally, publish packed, arrive (non-blocking)
            const float val = sig_apx(gi_cur + s);
            if (t < 2 * DD) rz_s[g].x = val; else rz_s[g].y = val;
            asm volatile("bar.arrive 1, 384;" ::: "memory");

            // warp 11: advance the gi readiness window in its dead time
            if (t >= 352 && (step & 31) == 0 && step) {
                const int l = t - 352;
                if (l <= 8) {
                    int c = (step >> 2) + l;
                    if (c > 255) c = 255;
                    volatile int* f = g_flag;
                    while (f[c] < epoch) __nanosleep(32);
                }
            }
        } else {
            // ---- n: fp32 FFMA2 matvec, 8 chains ----
            unsigned long long a0 = 0ull, a1 = 0ull, a2 = 0ull, a3 = 0ull;
            unsigned long long a4 = 0ull, a5 = 0ull, a6 = 0ull, a7 = 0ull;
            #pragma unroll
            for (int i = 0; i < 8; i++) {
                ulonglong2 hA = h2[4 * i];
                ulonglong2 hB = h2[4 * i + 1];
                ulonglong2 hC = h2[4 * i + 2];
                ulonglong2 hD = h2[4 * i + 3];
                a0 = ffma2(w2[8 * i + 0], hA.x, a0);
                a1 = ffma2(w2[8 * i + 1], hA.y, a1);
                a2 = ffma2(w2[8 * i + 2], hB.x, a2);
                a3 = ffma2(w2[8 * i + 3], hB.y, a3);
                a4 = ffma2(w2[8 * i + 4], hC.x, a4);
                a5 = ffma2(w2[8 * i + 5], hC.y, a5);
                a6 = ffma2(w2[8 * i + 6], hD.x, a6);
                a7 = ffma2(w2[8 * i + 7], hD.y, a7);
            }
            const unsigned long long p =
                fadd2(fadd2(fadd2(a0, a1), fadd2(a2, a3)),
                      fadd2(fadd2(a4, a5), fadd2(a6, a7)));
            const float s = f2lo(p) + f2hi(p) + bh;

            // wait for r/z, then the serial tail
            asm volatile("bar.sync 1, 384;" ::: "memory");
            const float2 rz = rz_s[g];
            const float nst = tanh_apx(fmaf(rz.x, s, gi_cur));  // s includes b_hh_n
            const float hv  = fmaf(rz.y, hreg - nst, nst);      // (1-z)n + z h
            hreg = hv;
            h_s[g] = hv;
            *(__half*)((char*)h16_s + 2 * g) = __float2half_rn(hv);
            out[step * DD + g] = hv;
        }
        // everyone: h (fp32 + fp16) must be written before the next matvec
        asm volatile("bar.sync 2, 384;" ::: "memory");
        gi_cur = gi_next;
    }
}

// ---------------- launch ----------------
extern "C" void kernel_launch(void* const* d_in, const int* in_sizes, int n_in,
                              void* d_out, int out_size) {
    const float* X    = (const float*)d_in[0];
    const float* Wq   = (const float*)d_in[1];
    const float* Wk   = (const float*)d_in[2];
    const float* v    = (const float*)d_in[3];
    const float* w_ih = (const float*)d_in[4];
    const float* w_hh = (const float*)d_in[5];
    const float* b_ih = (const float*)d_in[6];
    const float* b_hh = (const float*)d_in[7];
    float* out = (float*)d_out;

    // fork: prologue (qk -> att+gi) on a side stream; GRU starts immediately on
    // the main stream and consumes gi chunks via epoch flags.
    cudaStream_t s2;
    cudaStreamCreateWithFlags(&s2, cudaStreamNonBlocking);
    cudaEvent_t e1, e2;
    cudaEventCreateWithFlags(&e1, cudaEventDisableTiming);
    cudaEventCreateWithFlags(&e2, cudaEventDisableTiming);

    cudaEventRecord(e1, 0);
    cudaStreamWaitEvent(s2, e1, 0);

    qk_kernel<<<NN / 4, 256, 0, s2>>>(X, Wq, Wk);
    att_gi_kernel<<<NN / 4, 384, 0, s2>>>(X, v, w_ih, b_ih, b_hh);
    cudaEventRecord(e2, s2);

    gru_kernel<<<1, 384>>>(w_hh, b_hh, out);

    cudaStreamWaitEvent(0, e2, 0);
}

// round 14
// speedup vs baseline: 2.9998x; 1.1630x over previous
#include <cuda_runtime.h>
#include <cuda_bf16.h>
#include <cuda_fp16.h>
#include <cstdint>

#define NN 1024
#define DD 128

// ---------------- scratch (no allocations allowed) ----------------
__device__ float g_q[NN * DD];
__device__ float g_k[NN * DD];
__device__ float g_gi[NN * 3 * DD];

// progress flags (epoch-valued, monotonic => graph-replay-safe)
__device__ int g_flag[NN / 4 + 16];     // flag[c]==epoch when gi rows 4c..4c+3 ready
__device__ int g_epoch_att[NN / 4];     // per att+gi CTA launch counters
__device__ int g_epoch_gru;             // gru launch counter

// ---------------- helpers ----------------
__device__ __forceinline__ float tanh_apx(float x) {
    float y;
    asm("tanh.approx.f32 %0, %1;" : "=f"(y) : "f"(x));
    return y;
}
// sigmoid via one MUFU tanh (abs err ~1e-5; GRU is strongly contracting)
__device__ __forceinline__ float sig_apx(float x) {
    return fmaf(0.5f, tanh_apx(0.5f * x), 0.5f);
}

// half2 views of a packed u64 (register-free reinterpret)
__device__ __forceinline__ __half2 h2lo(unsigned long long a) {
    unsigned x = (unsigned)(a & 0xffffffffull);
    return *(__half2*)&x;
}
__device__ __forceinline__ __half2 h2hi(unsigned long long a) {
    unsigned x = (unsigned)(a >> 32);
    return *(__half2*)&x;
}

// block reductions for 384 threads (12 warps)
__device__ __forceinline__ float block_reduce_max(float v) {
    __shared__ float red[12];
    #pragma unroll
    for (int o = 16; o; o >>= 1) v = fmaxf(v, __shfl_xor_sync(0xffffffffu, v, o));
    if ((threadIdx.x & 31) == 0) red[threadIdx.x >> 5] = v;
    __syncthreads();
    float r = red[0];
    #pragma unroll
    for (int i = 1; i < 12; i++) r = fmaxf(r, red[i]);
    __syncthreads();
    return r;
}

__device__ __forceinline__ float block_reduce_sum(float v) {
    __shared__ float red[12];
    #pragma unroll
    for (int o = 16; o; o >>= 1) v += __shfl_xor_sync(0xffffffffu, v, o);
    if ((threadIdx.x & 31) == 0) red[threadIdx.x >> 5] = v;
    __syncthreads();
    float r = red[0];
    #pragma unroll
    for (int i = 1; i < 12; i++) r += red[i];
    __syncthreads();
    return r;
}

// ---------------- kernel 1: q = X@Wq^T, k = X@Wk^T (4 rows per CTA) ---------
__global__ void __launch_bounds__(256) qk_kernel(const float* __restrict__ X,
                                                 const float* __restrict__ Wq,
                                                 const float* __restrict__ Wk) {
    __shared__ __align__(16) float xs[4][DD];
    const int n0 = blockIdx.x * 4;
    const int tid = threadIdx.x;
    for (int idx = tid; idx < 4 * DD; idx += 256)
        xs[idx >> 7][idx & 127] = X[(n0 + (idx >> 7)) * DD + (idx & 127)];
    __syncthreads();

    const int s = tid >> 7;
    const int d = tid & 127;
    const float4* W4 = (const float4*)((s ? Wk : Wq) + d * DD);
    float acc[4] = {0.f, 0.f, 0.f, 0.f};

    #pragma unroll 8
    for (int c = 0; c < 32; c++) {
        float4 w = W4[c];
        #pragma unroll
        for (int r = 0; r < 4; r++) {
            float4 x = *(const float4*)&xs[r][c * 4];
            acc[r] += w.x * x.x + w.y * x.y + w.z * x.z + w.w * x.w;
        }
    }
    float* dst = s ? g_k : g_q;
    #pragma unroll
    for (int r = 0; r < 4; r++) dst[(n0 + r) * DD + d] = acc[r];
}

// ---------------- kernel 2: fused attention + gi, flag per 4-row chunk -------
__global__ void __launch_bounds__(384) att_gi_kernel(const float* __restrict__ X,
                                                     const float* __restrict__ v,
                                                     const float* __restrict__ w_ih,
                                                     const float* __restrict__ b_ih,
                                                     const float* __restrict__ b_hh) {
    __shared__ __align__(16) float q_s[4][DD];
    __shared__ __align__(16) float v_s[DD];
    __shared__ float sc[4][NN];
    __shared__ float inv_s[4];
    __shared__ __align__(16) float x4_s[4][DD];
    __shared__ __align__(16) float att_s[4][DD];
    __shared__ float part1[4][DD];
    __shared__ float part2[4][DD];
    __shared__ int ep_s;

    const int blk = blockIdx.x;
    const int i0 = blk * 4;
    const int tid = threadIdx.x;

    if (tid == 0) ep_s = atomicAdd(&g_epoch_att[blk], 1) + 1;

    for (int idx = tid; idx < 4 * DD; idx += 384) {
        q_s[idx >> 7][idx & 127] = g_q[(i0 + (idx >> 7)) * DD + (idx & 127)];
        x4_s[idx >> 7][idx & 127] = X[(i0 + (idx >> 7)) * DD + (idx & 127)];
    }
    if (tid < DD) v_s[tid] = v[tid];
    __syncthreads();

    // ---- phase A: scores ----
    for (int j = i0 + tid; j < NN; j += 384) {
        const float4* kr = (const float4*)(g_k + j * DD);
        float a0 = 0.f, a1 = 0.f, a2 = 0.f, a3 = 0.f;
        #pragma unroll 4
        for (int c = 0; c < 32; c++) {
            float4 kk = kr[c];
            float4 vv = *(const float4*)&v_s[c * 4];
            float4 q0 = *(const float4*)&q_s[0][c * 4];
            float4 q1 = *(const float4*)&q_s[1][c * 4];
            float4 q2 = *(const float4*)&q_s[2][c * 4];
            float4 q3 = *(const float4*)&q_s[3][c * 4];
            a0 += vv.x * tanh_apx(q0.x + kk.x) + vv.y * tanh_apx(q0.y + kk.y)
                + vv.z * tanh_apx(q0.z + kk.z) + vv.w * tanh_apx(q0.w + kk.w);
            a1 += vv.x * tanh_apx(q1.x + kk.x) + vv.y * tanh_apx(q1.y + kk.y)
                + vv.z * tanh_apx(q1.z + kk.z) + vv.w * tanh_apx(q1.w + kk.w);
            a2 += vv.x * tanh_apx(q2.x + kk.x) + vv.y * tanh_apx(q2.y + kk.y)
                + vv.z * tanh_apx(q2.z + kk.z) + vv.w * tanh_apx(q2.w + kk.w);
            a3 += vv.x * tanh_apx(q3.x + kk.x) + vv.y * tanh_apx(q3.y + kk.y)
                + vv.z * tanh_apx(q3.z + kk.z) + vv.w * tanh_apx(q3.w + kk.w);
        }
        const int jj = j - i0;
        sc[0][jj] = a0; sc[1][jj] = a1; sc[2][jj] = a2; sc[3][jj] = a3;
    }
    __syncthreads();

    // ---- phase B: per-row softmax over the suffix ----
    const int L = NN - i0;
    for (int r = 0; r < 4; r++) {
        float m = -1e30f;
        for (int idx = tid; idx < L; idx += 384) m = fmaxf(m, sc[r][idx]);
        const float bm = block_reduce_max(m);
        float ssum = 0.f;
        for (int idx = tid; idx < L; idx += 384) {
            float e = (idx < r) ? 0.0f : __expf(sc[r][idx] - bm);
            sc[r][idx] = e;
            ssum += e;
        }
        const float bs = block_reduce_sum(ssum);
        if (tid == 0) inv_s[r] = 1.0f / bs;
    }
    __syncthreads();

    // ---- phase C: att rows -> att_s ----
    {
        const int d = tid & 127;
        const int s3 = tid >> 7;     // 0,1,2
        float a[4] = {0.f, 0.f, 0.f, 0.f};
        for (int j = i0 + s3; j < NN; j += 3) {
            const float x = X[j * DD + d];
            const int jj = j - i0;
            a[0] += sc[0][jj] * x;
            a[1] += sc[1][jj] * x;
            a[2] += sc[2][jj] * x;
            a[3] += sc[3][jj] * x;
        }
        if (s3 == 1) {
            #pragma unroll
            for (int r = 0; r < 4; r++) part1[r][d] = a[r];
        } else if (s3 == 2) {
            #pragma unroll
            for (int r = 0; r < 4; r++) part2[r][d] = a[r];
        }
        __syncthreads();
        if (s3 == 0) {
            #pragma unroll
            for (int r = 0; r < 4; r++)
                att_s[r][d] = (a[r] + part1[r][d] + part2[r][d]) * inv_s[r];
        }
        __syncthreads();
    }

    // ---- phase D: gi rows (one gate per thread, 4 time rows) ----
    {
        const float4* w4 = (const float4*)(w_ih + tid * (2 * DD));
        float acc[4] = {0.f, 0.f, 0.f, 0.f};
        #pragma unroll 4
        for (int c = 0; c < 32; c++) {       // X half
            float4 w = w4[c];
            #pragma unroll
            for (int r = 0; r < 4; r++) {
                float4 iv = *(const float4*)&x4_s[r][c * 4];
                acc[r] += w.x * iv.x + w.y * iv.y + w.z * iv.z + w.w * iv.w;
            }
        }
        #pragma unroll 4
        for (int c = 0; c < 32; c++) {       // att half
            float4 w = w4[32 + c];
            #pragma unroll
            for (int r = 0; r < 4; r++) {
                float4 iv = *(const float4*)&att_s[r][c * 4];
                acc[r] += w.x * iv.x + w.y * iv.y + w.z * iv.z + w.w * iv.w;
            }
        }
        const float b = b_ih[tid] + ((tid < 2 * DD) ? b_hh[tid] : 0.0f);
        #pragma unroll
        for (int r = 0; r < 4; r++) g_gi[(i0 + r) * 384 + tid] = acc[r] + b;
    }

    __threadfence();
    __syncthreads();
    if (tid == 0) *(volatile int*)&g_flag[blk] = ep_s;
}

// ---------------- kernel 3: sequential GRU (overlapped consumer) -------------
// All 384 rows use fp16 HFMA2 matvec (rt 2) over fp16 h in smem.
// Warps 0-3  (t <  128): n-gate rows — fp32 chain-reduction tree (tanh slope 1
//   gives no damping, so accumulation stays fp32-accurate) + serial tail.
//   Exact fp32 h kept in hreg for the z*h recurrence term.
// Warps 4-11 (t >= 128): r/z rows — fp16 tree + sigmoid (1/4-slope damping).
// Warp 11 polls gi flags (one per lane) in its dead time after bar.arrive(1).
__global__ void __launch_bounds__(384, 1) gru_kernel(const float* __restrict__ w_hh,
                                                     const float* __restrict__ b_hh,
                                                     float* __restrict__ out) {
    __shared__ __align__(16) __half2 h16_s[DD / 2];
    __shared__ __align__(8) float2 rz_s[DD];      // .x = r gate, .y = z gate
    __shared__ int epoch_s;

    const int t = threadIdx.x;
    const bool is_n = (t < DD);
    const int g = t & 127;
    const int wrow = is_n ? (2 * DD + t) : (t - DD);   // own w_hh / gi row

    if (t == 0) epoch_s = atomicAdd(&g_epoch_gru, 1) + 1;

    // weights: fp16 quads (2 half2 per u64), 32 u64 per row
    unsigned long long w2[32];
    {
        const float2* wp = (const float2*)(w_hh + wrow * DD);
        #pragma unroll
        for (int i = 0; i < 32; i++) {
            __half2 q0 = __float22half2_rn(wp[2 * i]);
            __half2 q1 = __float22half2_rn(wp[2 * i + 1]);
            w2[i] = (unsigned long long)(*(unsigned*)&q0)
                  | ((unsigned long long)(*(unsigned*)&q1) << 32);
        }
    }
    const float bh = is_n ? b_hh[2 * DD + t] : 0.0f;   // r/z bias folded in gi

    if (t < DD / 2) ((unsigned*)h16_s)[t] = 0u;
    __syncthreads();
    const int epoch = epoch_s;

    const ulonglong2* h16q = (const ulonglong2*)h16_s;     // 4 half2 per 16B

    // initial wait: chunks 0..8 (steps 0..31 plus prefetch), parallel flags
    if (t <= 8) {
        volatile int* f = g_flag;
        while (f[t] < epoch) __nanosleep(32);
    }
    __syncthreads();

    float gi_cur = g_gi[wrow];   // step 0 gate input for this thread's own row
    float hreg = 0.0f;           // n-threads: exact fp32 h element

    for (int step = 0; step < NN; step++) {
        // prefetch next step's gi (hidden under the matvec)
        float gi_next = 0.0f;
        if (step + 1 < NN) gi_next = g_gi[(step + 1) * 384 + wrow];

        // ---- fp16 HFMA2 matvec, 8 chains (16 terms each) ----
        __half2 c0 = __float2half2_rn(0.f), c1 = c0, c2 = c0, c3 = c0;
        __half2 c4 = c0, c5 = c0, c6 = c0, c7 = c0;
        #pragma unroll
        for (int i = 0; i < 8; i++) {
            ulonglong2 hu = h16q[2 * i];        // cols 16i   .. 16i+7
            ulonglong2 hv = h16q[2 * i + 1];    // cols 16i+8 .. 16i+15
            const unsigned long long wa = w2[4 * i + 0];
            const unsigned long long wb = w2[4 * i + 1];
            const unsigned long long wc = w2[4 * i + 2];
            const unsigned long long wd = w2[4 * i + 3];
            c0 = __hfma2(h2lo(wa), h2lo(hu.x), c0);
            c1 = __hfma2(h2hi(wa), h2hi(hu.x), c1);
            c2 = __hfma2(h2lo(wb), h2lo(hu.y), c2);
            c3 = __hfma2(h2hi(wb), h2hi(hu.y), c3);
            c4 = __hfma2(h2lo(wc), h2lo(hv.x), c4);
            c5 = __hfma2(h2hi(wc), h2hi(hv.x), c5);
            c6 = __hfma2(h2lo(wd), h2lo(hv.y), c6);
            c7 = __hfma2(h2hi(wd), h2hi(hv.y), c7);
        }

        if (!is_n) {
            // r/z: fp16 reduction tree (sigmoid damping absorbs the error)
            __half2 d0 = __hadd2(__hadd2(c0, c1), __hadd2(c2, c3));
            __half2 d1 = __hadd2(__hadd2(c4, c5), __hadd2(c6, c7));
            __half2 dt = __hadd2(d0, d1);
            const float s = __low2float(dt) + __high2float(dt);

            const float val = sig_apx(gi_cur + s);
            if (t < 2 * DD) rz_s[g].x = val; else rz_s[g].y = val;
            asm volatile("bar.arrive 1, 384;" ::: "memory");

            // warp 11: advance the gi readiness window in its dead time
            if (t >= 352 && (step & 31) == 0 && step) {
                const int l = t - 352;
                if (l <= 8) {
                    int c = (step >> 2) + l;
                    if (c > 255) c = 255;
                    volatile int* f = g_flag;
                    while (f[c] < epoch) __nanosleep(32);
                }
            }
        } else {
            // n: fp32 reduction tree (no sigmoid damping -> keep accuracy)
            float2 f0 = __half22float2(c0), f1 = __half22float2(c1);
            float2 f2 = __half22float2(c2), f3 = __half22float2(c3);
            float2 f4 = __half22float2(c4), f5 = __half22float2(c5);
            float2 f6 = __half22float2(c6), f7 = __half22float2(c7);
            const float s = (((f0.x + f0.y) + (f1.x + f1.y))
                          +  ((f2.x + f2.y) + (f3.x + f3.y)))
                          + (((f4.x + f4.y) + (f5.x + f5.y))
                          +  ((f6.x + f6.y) + (f7.x + f7.y))) + bh;

            // wait for r/z, then the serial tail
            asm volatile("bar.sync 1, 384;" ::: "memory");
            const float2 rz = rz_s[g];
            const float nst = tanh_apx(fmaf(rz.x, s, gi_cur));  // s includes b_hh_n
            const float hv  = fmaf(rz.y, hreg - nst, nst);      // (1-z)n + z h
            hreg = hv;
            *(__half*)((char*)h16_s + 2 * g) = __float2half_rn(hv);
            out[step * DD + g] = hv;
        }
        // everyone: fp16 h must be written before the next matvec
        asm volatile("bar.sync 2, 384;" ::: "memory");
        gi_cur = gi_next;
    }
}

// ---------------- launch ----------------
extern "C" void kernel_launch(void* const* d_in, const int* in_sizes, int n_in,
                              void* d_out, int out_size) {
    const float* X    = (const float*)d_in[0];
    const float* Wq   = (const float*)d_in[1];
    const float* Wk   = (const float*)d_in[2];
    const float* v    = (const float*)d_in[3];
    const float* w_ih = (const float*)d_in[4];
    const float* w_hh = (const float*)d_in[5];
    const float* b_ih = (const float*)d_in[6];
    const float* b_hh = (const float*)d_in[7];
    float* out = (float*)d_out;

    // fork: prologue (qk -> att+gi) on a side stream; GRU starts immediately on
    // the main stream and consumes gi chunks via epoch flags.
    cudaStream_t s2;
    cudaStreamCreateWithFlags(&s2, cudaStreamNonBlocking);
    cudaEvent_t e1, e2;
    cudaEventCreateWithFlags(&e1, cudaEventDisableTiming);
    cudaEventCreateWithFlags(&e2, cudaEventDisableTiming);

    cudaEventRecord(e1, 0);
    cudaStreamWaitEvent(s2, e1, 0);

    qk_kernel<<<NN / 4, 256, 0, s2>>>(X, Wq, Wk);
    att_gi_kernel<<<NN / 4, 384, 0, s2>>>(X, v, w_ih, b_ih, b_hh);
    cudaEventRecord(e2, s2);

    gru_kernel<<<1, 384>>>(w_hh, b_hh, out);

    cudaStreamWaitEvent(0, e2, 0);
}